// round 2
// baseline (speedup 1.0000x reference)
#include <cuda_runtime.h>
#include <math.h>
#include <float.h>

// Problem constants
#define B   4
#define T   1024          // t1 == t2
#define F   1024
#define H   16
#define D   64            // F / H
#define MROWS (B*T)       // 4096

// GEMM tiling
#define TS 64
#define KS 16

// Scratch (allocation-free rule: __device__ globals)
__device__ float g_q[(size_t)B*T*F];
__device__ float g_k[(size_t)B*T*F];
__device__ float g_v[(size_t)B*T*F];
__device__ float g_x[(size_t)B*T*F];
__device__ int   g_mask_code;

// ---------------------------------------------------------------------------
// Mask dtype detection: scan first 1M u32 words of the mask buffer.
//   word == 0x3F800000                -> float32 mask  (bit 1)
//   word > 1 (and not 0x3F800000)    -> packed uint8/bool mask (bit 0)
//   otherwise (all words 0/1)        -> int32 mask (code 0)
// ---------------------------------------------------------------------------
__global__ void detect_mask(const unsigned int* __restrict__ m)
{
    unsigned int w = m[blockIdx.x * blockDim.x + threadIdx.x];
    int f = 0;
    if (w == 0x3F800000u)      f = 2;
    else if (w > 1u)           f = 1;
    if (f) atomicOr(&g_mask_code, f);
}

// ---------------------------------------------------------------------------
// Kernel 1: QKV projections.  C = A(M,K) @ W(K,N) + bias.  M=4096,K=N=1024.
// grid (N/64, M/64, 3)
// ---------------------------------------------------------------------------
__global__ void qkv_gemm(const float* __restrict__ Aq, const float* __restrict__ Ak,
                         const float* __restrict__ Av,
                         const float* __restrict__ Wq, const float* __restrict__ Wk,
                         const float* __restrict__ Wv,
                         const float* __restrict__ bq, const float* __restrict__ bk,
                         const float* __restrict__ bv)
{
    const int which = blockIdx.z;
    const float* A    = (which == 0) ? Aq : (which == 1) ? Ak : Av;
    const float* W    = (which == 0) ? Wq : (which == 1) ? Wk : Wv;
    const float* bias = (which == 0) ? bq : (which == 1) ? bk : bv;
    float* O          = (which == 0) ? g_q : (which == 1) ? g_k : g_v;

    const int K = F, N = F;
    __shared__ float As[KS][TS];
    __shared__ float Bs[KS][TS];

    const int t  = threadIdx.x;
    const int tx = t & 15;
    const int ty = t >> 4;
    const int tile_n = blockIdx.x * TS;
    const int tile_m = blockIdx.y * TS;

    float acc[4][4] = {};

    for (int kt = 0; kt < K; kt += KS) {
        {   // A tile: 64 rows x 16 cols -> As[k][m]
            int m  = t >> 2;
            int q4 = (t & 3) * 4;
            float4 a = *(const float4*)(A + (size_t)(tile_m + m) * K + kt + q4);
            As[q4+0][m] = a.x; As[q4+1][m] = a.y; As[q4+2][m] = a.z; As[q4+3][m] = a.w;
        }
        {   // W tile: 16 rows x 64 cols -> Bs[k][n]
            int k  = t >> 4;
            int n4 = (t & 15) * 4;
            *(float4*)&Bs[k][n4] = *(const float4*)(W + (size_t)(kt + k) * N + tile_n + n4);
        }
        __syncthreads();
        #pragma unroll
        for (int k = 0; k < KS; k++) {
            float a[4], b[4];
            #pragma unroll
            for (int i = 0; i < 4; i++) a[i] = As[k][ty*4 + i];
            #pragma unroll
            for (int j = 0; j < 4; j++) b[j] = Bs[k][tx*4 + j];
            #pragma unroll
            for (int i = 0; i < 4; i++)
                #pragma unroll
                for (int j = 0; j < 4; j++)
                    acc[i][j] += a[i] * b[j];
        }
        __syncthreads();
    }

    #pragma unroll
    for (int i = 0; i < 4; i++) {
        int m = tile_m + ty*4 + i;
        #pragma unroll
        for (int j = 0; j < 4; j++) {
            int n = tile_n + tx*4 + j;
            O[(size_t)m * N + n] = acc[i][j] + bias[n];
        }
    }
}

// ---------------------------------------------------------------------------
// Kernel 2: scores[h,b,i,j] = (q[b,i,h,:] . k[b,j,h,:]) / 8    (NT GEMM, K=64)
// grid (16,16,64) with z = h*4 + bb
// ---------------------------------------------------------------------------
__global__ void scores_gemm(float* __restrict__ attn)
{
    const int z  = blockIdx.z;
    const int h  = z >> 2;
    const int bb = z & 3;
    const float* A  = g_q + (size_t)bb * T * F + h * D;  // row stride F
    const float* Bm = g_k + (size_t)bb * T * F + h * D;  // row stride F

    __shared__ float As[KS][TS];
    __shared__ float Bs[KS][TS];

    const int t  = threadIdx.x;
    const int tx = t & 15;
    const int ty = t >> 4;
    const int tile_n = blockIdx.x * TS;
    const int tile_m = blockIdx.y * TS;

    float acc[4][4] = {};

    for (int kt = 0; kt < D; kt += KS) {
        {   // q tile -> As[k][m]
            int m  = t >> 2;
            int q4 = (t & 3) * 4;
            float4 a = *(const float4*)(A + (size_t)(tile_m + m) * F + kt + q4);
            As[q4+0][m] = a.x; As[q4+1][m] = a.y; As[q4+2][m] = a.z; As[q4+3][m] = a.w;
        }
        {   // k tile (transposed use) -> Bs[k][n]
            int n  = t >> 2;
            int q4 = (t & 3) * 4;
            float4 bv = *(const float4*)(Bm + (size_t)(tile_n + n) * F + kt + q4);
            Bs[q4+0][n] = bv.x; Bs[q4+1][n] = bv.y; Bs[q4+2][n] = bv.z; Bs[q4+3][n] = bv.w;
        }
        __syncthreads();
        #pragma unroll
        for (int k = 0; k < KS; k++) {
            float a[4], b[4];
            #pragma unroll
            for (int i = 0; i < 4; i++) a[i] = As[k][ty*4 + i];
            #pragma unroll
            for (int j = 0; j < 4; j++) b[j] = Bs[k][tx*4 + j];
            #pragma unroll
            for (int i = 0; i < 4; i++)
                #pragma unroll
                for (int j = 0; j < 4; j++)
                    acc[i][j] += a[i] * b[j];
        }
        __syncthreads();
    }

    float* O = attn + (size_t)z * T * T;
    const float scale = 0.125f;  // 1/sqrt(64)
    #pragma unroll
    for (int i = 0; i < 4; i++) {
        int m = tile_m + ty*4 + i;
        #pragma unroll
        for (int j = 0; j < 4; j++) {
            int n = tile_n + tx*4 + j;
            O[(size_t)m * T + n] = acc[i][j] * scale;
        }
    }
}

// ---------------------------------------------------------------------------
// Kernel 3: masked softmax (in place on attn), then zero masked entries and
// scale by query_mask. One block (256 thr) per row; 4 elems/thread.
// Mask dtype chosen at runtime from g_mask_code.
// ---------------------------------------------------------------------------
__device__ __forceinline__ float warpMax(float v) {
    #pragma unroll
    for (int o = 16; o; o >>= 1) v = fmaxf(v, __shfl_xor_sync(0xffffffffu, v, o));
    return v;
}
__device__ __forceinline__ float warpSum(float v) {
    #pragma unroll
    for (int o = 16; o; o >>= 1) v += __shfl_xor_sync(0xffffffffu, v, o);
    return v;
}

__global__ void softmax_mask(float* __restrict__ attn,
                             const void* __restrict__ mask,
                             const float* __restrict__ query_mask)
{
    const int r  = blockIdx.x;        // 0 .. 65535  (z*1024 + i)
    const int z  = r >> 10;
    const int bb = z & 3;
    const int i  = r & 1023;
    const size_t base = (size_t)r * T;
    const int t = threadIdx.x;

    float4 s = ((const float4*)(attn + base))[t];

    // Read 4 mask bits according to detected dtype
    int m0, m1, m2, m3;
    const int code = g_mask_code;
    if (code & 2) {         // float32 mask
        float4 mf = ((const float4*)((const float*)mask + base))[t];
        m0 = (mf.x != 0.f); m1 = (mf.y != 0.f); m2 = (mf.z != 0.f); m3 = (mf.w != 0.f);
    } else if (code & 1) {  // packed uint8 / bool mask
        uchar4 mc = ((const uchar4*)((const unsigned char*)mask + base))[t];
        m0 = mc.x; m1 = mc.y; m2 = mc.z; m3 = mc.w;
    } else {                // int32 mask
        int4 mi = ((const int4*)((const int*)mask + base))[t];
        m0 = mi.x; m1 = mi.y; m2 = mi.z; m3 = mi.w;
    }

    float v0 = m0 ? -FLT_MAX : s.x;
    float v1 = m1 ? -FLT_MAX : s.y;
    float v2 = m2 ? -FLT_MAX : s.z;
    float v3 = m3 ? -FLT_MAX : s.w;
    float lm = fmaxf(fmaxf(v0, v1), fmaxf(v2, v3));

    __shared__ float red[8];
    float wm = warpMax(lm);
    if ((t & 31) == 0) red[t >> 5] = wm;
    __syncthreads();
    float bmax = red[0];
    #pragma unroll
    for (int w = 1; w < 8; w++) bmax = fmaxf(bmax, red[w]);
    __syncthreads();

    float p0 = m0 ? 0.f : __expf(s.x - bmax);
    float p1 = m1 ? 0.f : __expf(s.y - bmax);
    float p2 = m2 ? 0.f : __expf(s.z - bmax);
    float p3 = m3 ? 0.f : __expf(s.w - bmax);

    float ws = warpSum(p0 + p1 + p2 + p3);
    if ((t & 31) == 0) red[t >> 5] = ws;
    __syncthreads();
    float bsum = 0.f;
    #pragma unroll
    for (int w = 0; w < 8; w++) bsum += red[w];

    float qm  = query_mask[bb * T + i];
    float inv = (bsum > 0.f) ? (qm / bsum) : 0.f;

    float4 o;
    o.x = p0 * inv; o.y = p1 * inv; o.z = p2 * inv; o.w = p3 * inv;
    ((float4*)(attn + base))[t] = o;
}

// ---------------------------------------------------------------------------
// Kernel 4: x[b,i,h,:] = sum_j attn[h,b,i,j] * v[b,j,h,:]   (NN, N=64,K=1024)
// grid (1,16,64)
// ---------------------------------------------------------------------------
__global__ void av_gemm(const float* __restrict__ attn)
{
    const int z  = blockIdx.z;
    const int h  = z >> 2;
    const int bb = z & 3;
    const float* A  = attn + (size_t)z * T * T;          // (T,T) row-major
    const float* Bm = g_v + (size_t)bb * T * F + h * D;  // (T,D) row stride F

    __shared__ float As[KS][TS];
    __shared__ float Bs[KS][TS];

    const int t  = threadIdx.x;
    const int tx = t & 15;
    const int ty = t >> 4;
    const int tile_m = blockIdx.y * TS;

    float acc[4][4] = {};

    for (int kt = 0; kt < T; kt += KS) {
        {
            int m  = t >> 2;
            int q4 = (t & 3) * 4;
            float4 a = *(const float4*)(A + (size_t)(tile_m + m) * T + kt + q4);
            As[q4+0][m] = a.x; As[q4+1][m] = a.y; As[q4+2][m] = a.z; As[q4+3][m] = a.w;
        }
        {
            int k  = t >> 4;
            int n4 = (t & 15) * 4;
            *(float4*)&Bs[k][n4] = *(const float4*)(Bm + (size_t)(kt + k) * F + n4);
        }
        __syncthreads();
        #pragma unroll
        for (int k = 0; k < KS; k++) {
            float a[4], b[4];
            #pragma unroll
            for (int i = 0; i < 4; i++) a[i] = As[k][ty*4 + i];
            #pragma unroll
            for (int j = 0; j < 4; j++) b[j] = Bs[k][tx*4 + j];
            #pragma unroll
            for (int i = 0; i < 4; i++)
                #pragma unroll
                for (int j = 0; j < 4; j++)
                    acc[i][j] += a[i] * b[j];
        }
        __syncthreads();
    }

    float* O = g_x + (size_t)bb * T * F + h * D;  // row stride F
    #pragma unroll
    for (int i = 0; i < 4; i++) {
        int m = tile_m + ty*4 + i;
        #pragma unroll
        for (int j = 0; j < 4; j++) {
            int n = tx*4 + j;
            O[(size_t)m * F + n] = acc[i][j];
        }
    }
}

// ---------------------------------------------------------------------------
// Kernel 5: out = concat(x, query) @ Wf + bf + query.  M=4096,N=1024,K=2048.
// grid (16,64)
// ---------------------------------------------------------------------------
__global__ void final_gemm(const float* __restrict__ query,
                           const float* __restrict__ Wf,
                           const float* __restrict__ bf,
                           float* __restrict__ out)
{
    const int K = 2 * F, N = F;
    __shared__ float As[KS][TS];
    __shared__ float Bs[KS][TS];

    const int t  = threadIdx.x;
    const int tx = t & 15;
    const int ty = t >> 4;
    const int tile_n = blockIdx.x * TS;
    const int tile_m = blockIdx.y * TS;

    float acc[4][4] = {};

    for (int kt = 0; kt < K; kt += KS) {
        const float* Asrc = (kt < F) ? g_x : query;
        const int koff    = (kt < F) ? kt : (kt - F);
        {
            int m  = t >> 2;
            int q4 = (t & 3) * 4;
            float4 a = *(const float4*)(Asrc + (size_t)(tile_m + m) * F + koff + q4);
            As[q4+0][m] = a.x; As[q4+1][m] = a.y; As[q4+2][m] = a.z; As[q4+3][m] = a.w;
        }
        {
            int k  = t >> 4;
            int n4 = (t & 15) * 4;
            *(float4*)&Bs[k][n4] = *(const float4*)(Wf + (size_t)(kt + k) * N + tile_n + n4);
        }
        __syncthreads();
        #pragma unroll
        for (int k = 0; k < KS; k++) {
            float a[4], b[4];
            #pragma unroll
            for (int i = 0; i < 4; i++) a[i] = As[k][ty*4 + i];
            #pragma unroll
            for (int j = 0; j < 4; j++) b[j] = Bs[k][tx*4 + j];
            #pragma unroll
            for (int i = 0; i < 4; i++)
                #pragma unroll
                for (int j = 0; j < 4; j++)
                    acc[i][j] += a[i] * b[j];
        }
        __syncthreads();
    }

    #pragma unroll
    for (int i = 0; i < 4; i++) {
        int m = tile_m + ty*4 + i;
        #pragma unroll
        for (int j = 0; j < 4; j++) {
            int n = tile_n + tx*4 + j;
            out[(size_t)m * N + n] = acc[i][j] + bf[n] + query[(size_t)m * N + n];
        }
    }
}

// ---------------------------------------------------------------------------
extern "C" void kernel_launch(void* const* d_in, const int* in_sizes, int n_in,
                              void* d_out, int out_size)
{
    const float* query        = (const float*)d_in[0];
    const float* key          = (const float*)d_in[1];
    const float* value        = (const float*)d_in[2];
    const void*  mask         = d_in[3];
    const float* query_mask   = (const float*)d_in[4];
    const float* Wq = (const float*)d_in[5];
    const float* bq = (const float*)d_in[6];
    const float* Wk = (const float*)d_in[7];
    const float* bk = (const float*)d_in[8];
    const float* Wv = (const float*)d_in[9];
    const float* bv = (const float*)d_in[10];
    const float* Wf = (const float*)d_in[11];
    const float* bf = (const float*)d_in[12];

    float* out  = (float*)d_out;
    float* attn = out + (size_t)B * T * F;   // second output, (H*B, T, T)

    // 0) reset + run mask dtype detection (first 4MB of mask buffer)
    void* code_addr = nullptr;
    cudaGetSymbolAddress(&code_addr, g_mask_code);
    cudaMemsetAsync(code_addr, 0, sizeof(int));
    detect_mask<<<4096, 256>>>((const unsigned int*)mask);

    // 1) QKV projections
    qkv_gemm<<<dim3(F/TS, MROWS/TS, 3), 256>>>(query, key, value,
                                               Wq, Wk, Wv, bq, bk, bv);
    // 2) scaled scores -> attn region (raw)
    scores_gemm<<<dim3(T/TS, T/TS, H*B), 256>>>(attn);
    // 3) masked softmax in place (+ mask-zeroing + query_mask scale)
    softmax_mask<<<H*B*T, 256>>>(attn, mask, query_mask);
    // 4) x = attn @ v
    av_gemm<<<dim3(1, T/TS, H*B), 256>>>(attn);
    // 5) out = concat(x, query) @ Wf + bf + query
    final_gemm<<<dim3(F/TS, MROWS/TS), 256>>>(query, Wf, bf, out);
}